// round 9
// baseline (speedup 1.0000x reference)
#include <cuda_runtime.h>
#include <cuda_bf16.h>
#include <cstdint>

#define BATCH_ 8192
#define DIM_   768
#define DICT_  32768
#define TOPK_  32
#define CAND   64

// Plain bf16 filter GEMM (refine makes the final result exact): K = 768
#define K2      768
#define TM      128
#define TN      256
#define BK      32
#define NCH     (K2 / BK)          // 24
#define ASTRIDE 80                 // 64B row + 16B pad: conflict-free ldmatrix
#define A_STAGE (TM * ASTRIDE)     // 10240
#define B_STAGE (TN * ASTRIDE)     // 20480
#define STAGE_BYTES (A_STAGE + B_STAGE)    // 30720
#define STAGES  3
#define SMEM_GEMM (STAGES * STAGE_BYTES)   // 92160

// ---------------------------------------------------------------------------
// Device scratch (allocation-free rule: __device__ globals)
// ---------------------------------------------------------------------------
__device__ __nv_bfloat16 g_XA[(size_t)BATCH_ * K2];    // bf16(X)
__device__ __nv_bfloat16 g_WB[(size_t)DICT_  * K2];    // bf16(W_enc)
__device__ __nv_bfloat16 g_Z [(size_t)BATCH_ * DICT_]; // approx z (bf16)
__device__ float g_WdT[(size_t)DICT_ * DIM_];          // W_dec transposed
__device__ int   g_cand[BATCH_ * CAND];                // approx top-64 indices
__device__ float g_vals[BATCH_ * TOPK_];
__device__ int   g_idx [BATCH_ * TOPK_];

// ---------------------------------------------------------------------------
// PTX helpers (sm_80+ baseline only — NO tcgen05: harness targets sm_103)
// ---------------------------------------------------------------------------
__device__ __forceinline__ uint32_t smem_u32(const void* p) {
    return (uint32_t)__cvta_generic_to_shared(p);
}

__device__ __forceinline__ void cp_async16(uint32_t dst, const void* src) {
    asm volatile("cp.async.cg.shared.global [%0], [%1], 16;"
                 :: "r"(dst), "l"(src) : "memory");
}

__device__ __forceinline__ void ldsm_x4(uint32_t r[4], uint32_t addr) {
    asm volatile("ldmatrix.sync.aligned.m8n8.x4.shared.b16 {%0,%1,%2,%3}, [%4];"
                 : "=r"(r[0]), "=r"(r[1]), "=r"(r[2]), "=r"(r[3]) : "r"(addr));
}

__device__ __forceinline__ void mma16816(float c[4], const uint32_t a[4],
                                         const uint32_t b[2]) {
    asm volatile(
        "mma.sync.aligned.m16n8k16.row.col.f32.bf16.bf16.f32 "
        "{%0,%1,%2,%3}, {%4,%5,%6,%7}, {%8,%9}, {%0,%1,%2,%3};"
        : "+f"(c[0]), "+f"(c[1]), "+f"(c[2]), "+f"(c[3])
        : "r"(a[0]), "r"(a[1]), "r"(a[2]), "r"(a[3]), "r"(b[0]), "r"(b[1]));
}

// ---------------------------------------------------------------------------
// fp32 -> bf16 conversions (vectorized) + output-zero kernel
// ---------------------------------------------------------------------------
__global__ __launch_bounds__(256) void cvt_x(const float* __restrict__ X) {
    int i = blockIdx.x * 256 + threadIdx.x;
    if (i >= BATCH_ * DIM_ / 4) return;
    float4 v = reinterpret_cast<const float4*>(X)[i];
    reinterpret_cast<__nv_bfloat162*>(g_XA)[i*2]   = __float22bfloat162_rn(make_float2(v.x, v.y));
    reinterpret_cast<__nv_bfloat162*>(g_XA)[i*2+1] = __float22bfloat162_rn(make_float2(v.z, v.w));
}

__global__ __launch_bounds__(256) void cvt_w(const float* __restrict__ W) {
    int i = blockIdx.x * 256 + threadIdx.x;
    if (i >= DICT_ * DIM_ / 4) return;
    float4 v = reinterpret_cast<const float4*>(W)[i];
    reinterpret_cast<__nv_bfloat162*>(g_WB)[i*2]   = __float22bfloat162_rn(make_float2(v.x, v.y));
    reinterpret_cast<__nv_bfloat162*>(g_WB)[i*2+1] = __float22bfloat162_rn(make_float2(v.z, v.w));
}

__global__ __launch_bounds__(256) void zero_enc(float* __restrict__ enc) {
    size_t i = (size_t)blockIdx.x * 256 + threadIdx.x;
    reinterpret_cast<float4*>(enc)[i] = make_float4(0.f, 0.f, 0.f, 0.f);
}

// ---------------------------------------------------------------------------
// HMMA filter GEMM: Z[m,n] = bf16( sum_k XA[m,k]*WB[n,k] + bias[n] )
// CTA tile 128x256, 8 warps (2x4), warp tile 64x64, BK=32,
// cp.async 3-slot ring with prefetch distance 2.
// ---------------------------------------------------------------------------
__device__ __forceinline__ void load_stage_g(uint32_t sbase, int slot, int k0,
                                             int m0, int n0, int tid) {
    uint32_t sA = sbase + slot * STAGE_BYTES;
    uint32_t sB = sA + A_STAGE;
    const __nv_bfloat16* Ag = g_XA + (size_t)m0 * K2 + k0;
    const __nv_bfloat16* Bg = g_WB + (size_t)n0 * K2 + k0;
    const int lrow = tid >> 2;       // 0..63
    const int lch  = tid & 3;        // 16B chunk within 64B row
    #pragma unroll
    for (int it = 0; it < 2; it++) {
        int row = lrow + it * 64;
        cp_async16(sA + row * ASTRIDE + lch * 16, Ag + (size_t)row * K2 + lch * 8);
    }
    #pragma unroll
    for (int it = 0; it < 4; it++) {
        int row = lrow + it * 64;
        cp_async16(sB + row * ASTRIDE + lch * 16, Bg + (size_t)row * K2 + lch * 8);
    }
}

__global__ __launch_bounds__(256, 1) void encode_gemm_mma(
    const float* __restrict__ bias)
{
    extern __shared__ char smem[];
    const uint32_t sbase = smem_u32(smem);
    const int tid  = threadIdx.x;
    const int lane = tid & 31;
    const int wid  = tid >> 5;
    const int m0 = blockIdx.x * TM;
    const int n0 = blockIdx.y * TN;
    const int wm = (wid & 1) * 64;    // warp M offset
    const int wn = (wid >> 1) * 64;   // warp N offset (4 warps across N)

    float acc[4][8][4];
    #pragma unroll
    for (int mi = 0; mi < 4; mi++)
        #pragma unroll
        for (int ni = 0; ni < 8; ni++)
            #pragma unroll
            for (int r = 0; r < 4; r++) acc[mi][ni][r] = 0.f;

    // Prologue: chunks 0,1 into slots 0,1
    #pragma unroll
    for (int s = 0; s < 2; s++) {
        load_stage_g(sbase, s, s * BK, m0, n0, tid);
        asm volatile("cp.async.commit_group;" ::: "memory");
    }

    for (int i = 0; i < NCH; i++) {
        asm volatile("cp.async.wait_group 1;" ::: "memory");
        __syncthreads();   // chunk i ready in slot i%3; slot (i+2)%3 free

        if (i + 2 < NCH)
            load_stage_g(sbase, (i + 2) % 3, (i + 2) * BK, m0, n0, tid);
        asm volatile("cp.async.commit_group;" ::: "memory");

        const uint32_t sA = sbase + (i % 3) * STAGE_BYTES;
        const uint32_t sB = sA + A_STAGE;
        const int g = lane >> 3;

        #pragma unroll
        for (int ks = 0; ks < 2; ks++) {
            uint32_t a[4][4], b[4][4];
            #pragma unroll
            for (int mi = 0; mi < 4; mi++)
                ldsm_x4(a[mi], sA + (wm + mi * 16 + (lane & 15)) * ASTRIDE
                               + ks * 32 + (lane >> 4) * 16);
            #pragma unroll
            for (int nj = 0; nj < 4; nj++)
                ldsm_x4(b[nj], sB + (wn + nj * 16 + (g >> 1) * 8 + (lane & 7)) * ASTRIDE
                               + ks * 32 + (g & 1) * 16);
            #pragma unroll
            for (int mi = 0; mi < 4; mi++)
                #pragma unroll
                for (int ni = 0; ni < 8; ni++)
                    mma16816(acc[mi][ni], a[mi], &b[ni >> 1][(ni & 1) * 2]);
        }
    }

    // Epilogue: + bias, convert to bf16, write Z
    #pragma unroll
    for (int mi = 0; mi < 4; mi++) {
        int r0 = m0 + wm + mi * 16 + (lane >> 2);
        #pragma unroll
        for (int ni = 0; ni < 8; ni++) {
            int col = n0 + wn + ni * 8 + (lane & 3) * 2;
            float2 bv = *reinterpret_cast<const float2*>(bias + col);
            __nv_bfloat162 v0 = __float22bfloat162_rn(
                make_float2(acc[mi][ni][0] + bv.x, acc[mi][ni][1] + bv.y));
            __nv_bfloat162 v1 = __float22bfloat162_rn(
                make_float2(acc[mi][ni][2] + bv.x, acc[mi][ni][3] + bv.y));
            *reinterpret_cast<__nv_bfloat162*>(g_Z + (size_t)r0 * DICT_ + col)       = v0;
            *reinterpret_cast<__nv_bfloat162*>(g_Z + (size_t)(r0 + 8) * DICT_ + col) = v1;
        }
    }
}

// ---------------------------------------------------------------------------
// Candidate selection on bf16 z: top-CAND indices per row.
// Three FULL scans of the 64KB smem row (no capped lists -> no overflow).
// Histogram atomics warp-aggregated via __match_any_sync (exponent-clustered
// buckets would otherwise serialize the smem atomic unit).
// ---------------------------------------------------------------------------
__device__ __forceinline__ unsigned key16(unsigned h) {
    return h ^ ((h & 0x8000u) ? 0xFFFFu : 0x8000u);
}

__device__ __forceinline__ void hist_add(unsigned* hist, unsigned bucket,
                                         unsigned member) {
    unsigned m = __match_any_sync(member, bucket);
    if ((__ffs(m) - 1) == (int)(threadIdx.x & 31))
        atomicAdd(&hist[bucket], (unsigned)__popc(m));
}

__global__ __launch_bounds__(256) void topk_cand()
{
    extern __shared__ unsigned short srow16[];   // DICT_ uint16 = 64KB
    const int row = blockIdx.x;
    const int tid = threadIdx.x;

    {
        const uint4* z4 = reinterpret_cast<const uint4*>(g_Z + (size_t)row * DICT_);
        uint4* s4 = reinterpret_cast<uint4*>(srow16);
        for (int i = tid; i < DICT_ * 2 / 16; i += 256) s4[i] = z4[i];
    }

    __shared__ unsigned hist[256];
    __shared__ int s_b, s_k, s_b2, s_k2, nslot, eq2;

    if (tid == 0) { nslot = 0; eq2 = 0; }
    hist[tid] = 0;
    __syncthreads();

    // scan1: high-byte histogram, warp-aggregated (all lanes active)
    for (int i = tid; i < DICT_ / 2; i += 256) {
        unsigned v = reinterpret_cast<unsigned*>(srow16)[i];
        hist_add(hist, key16(v & 0xFFFFu) >> 8, 0xFFFFFFFFu);
        hist_add(hist, key16(v >> 16) >> 8, 0xFFFFFFFFu);
    }
    __syncthreads();
    if (tid == 0) {
        int kk = CAND, b = 255;
        for (;; b--) { int c = (int)hist[b]; if (c >= kk) break; kk -= c; }
        s_b = b; s_k = kk;
    }
    __syncthreads();
    const unsigned bhi = (unsigned)s_b;
    const int keq1 = s_k;
    hist[tid] = 0;
    __syncthreads();

    // scan2: low-byte histogram restricted to hi == bhi (sparse; aggregated)
    for (int i = tid; i < DICT_ / 2; i += 256) {
        unsigned v = reinterpret_cast<unsigned*>(srow16)[i];
        unsigned k0 = key16(v & 0xFFFFu);
        unsigned k1 = key16(v >> 16);
        unsigned act0 = __ballot_sync(0xFFFFFFFFu, (k0 >> 8) == bhi);
        if ((k0 >> 8) == bhi) hist_add(hist, k0 & 0xFFu, act0);
        unsigned act1 = __ballot_sync(0xFFFFFFFFu, (k1 >> 8) == bhi);
        if ((k1 >> 8) == bhi) hist_add(hist, k1 & 0xFFu, act1);
    }
    __syncthreads();
    if (tid == 0) {
        int kk = keq1, b = 255;
        for (;; b--) { int c = (int)hist[b]; if (c >= kk) break; kk -= c; }
        s_b2 = b; s_k2 = kk;
    }
    __syncthreads();
    const unsigned blo = (unsigned)s_b2;
    const int keq2 = s_k2;

    // scan3: emit exactly CAND candidate indices
    for (int i = tid; i < DICT_; i += 256) {
        unsigned k = key16(srow16[i]);
        unsigned hi = k >> 8, lo = k & 0xFFu;
        if (hi > bhi || (hi == bhi && lo > blo)) {
            int s = atomicAdd(&nslot, 1);
            g_cand[row * CAND + s] = i;
        } else if (hi == bhi && lo == blo) {
            int e = atomicAdd(&eq2, 1);
            if (e < keq2) {
                int s = atomicAdd(&nslot, 1);
                g_cand[row * CAND + s] = i;
            }
        }
    }
}

// ---------------------------------------------------------------------------
// Refine: exact fp32 recompute of the CAND candidates, exact top-32 with
// first-index tie-break, scatter into enc + decode buffers.
// ---------------------------------------------------------------------------
__device__ __forceinline__ unsigned key_of(float f) {
    unsigned u = __float_as_uint(f);
    return u ^ ((u & 0x80000000u) ? 0xFFFFFFFFu : 0x80000000u);
}

__device__ __forceinline__ unsigned long long sel_key(float v, int idx) {
    return ((unsigned long long)key_of(v) << 32) | (unsigned)(0x7FFFFFFF - idx);
}

__global__ __launch_bounds__(256) void refine_kernel(
    const float* __restrict__ X, const float* __restrict__ W_enc,
    const float* __restrict__ b_enc, float* __restrict__ enc)
{
    const int row = blockIdx.x;
    const int tid = threadIdx.x;
    const int w = tid >> 5, lane = tid & 31;
    __shared__ float sx[DIM_];
    __shared__ float cv[CAND];
    __shared__ int   ci[CAND];

    for (int i = tid; i < DIM_ / 4; i += 256)
        reinterpret_cast<float4*>(sx)[i] =
            reinterpret_cast<const float4*>(X + (size_t)row * DIM_)[i];
    if (tid < CAND) ci[tid] = g_cand[row * CAND + tid];
    __syncthreads();

    for (int c = w; c < CAND; c += 8) {
        const float* wr = W_enc + (size_t)ci[c] * DIM_;
        float s = 0.f;
        #pragma unroll
        for (int j = lane * 4; j < DIM_; j += 128) {
            float4 a = *reinterpret_cast<const float4*>(sx + j);
            float4 b = *reinterpret_cast<const float4*>(wr + j);
            s = fmaf(a.x, b.x, s); s = fmaf(a.y, b.y, s);
            s = fmaf(a.z, b.z, s); s = fmaf(a.w, b.w, s);
        }
        #pragma unroll
        for (int o = 16; o; o >>= 1) s += __shfl_xor_sync(0xFFFFFFFFu, s, o);
        if (lane == 0) cv[c] = s + b_enc[ci[c]];
    }
    __syncthreads();

    if (w == 0) {
        unsigned long long ka = sel_key(cv[lane],      ci[lane]);
        unsigned long long kb = sel_key(cv[lane + 32], ci[lane + 32]);
        for (int s = 0; s < TOPK_; s++) {
            unsigned long long m = ka > kb ? ka : kb;
            #pragma unroll
            for (int o = 16; o; o >>= 1) {
                unsigned long long t = __shfl_xor_sync(0xFFFFFFFFu, m, o);
                if (t > m) m = t;
            }
            if (ka == m) {
                int idx = ci[lane]; float v = cv[lane];
                enc[(size_t)row * DICT_ + idx] = v;
                g_vals[row * TOPK_ + s] = v;
                g_idx [row * TOPK_ + s] = idx;
                ka = 0ull;
            } else if (kb == m) {
                int idx = ci[lane + 32]; float v = cv[lane + 32];
                enc[(size_t)row * DICT_ + idx] = v;
                g_vals[row * TOPK_ + s] = v;
                g_idx [row * TOPK_ + s] = idx;
                kb = 0ull;
            }
        }
    }
}

// ---------------------------------------------------------------------------
// W_dec [DIM, DICT] -> g_WdT [DICT, DIM]
// ---------------------------------------------------------------------------
__global__ void transpose_wdec(const float* __restrict__ Wd)
{
    __shared__ float tile[32][33];
    int bx = blockIdx.x * 32;
    int by = blockIdx.y * 32;
    int tx = threadIdx.x, ty = threadIdx.y;
    #pragma unroll
    for (int j = 0; j < 32; j += 8)
        tile[ty + j][tx] = Wd[(size_t)(by + ty + j) * DICT_ + bx + tx];
    __syncthreads();
    #pragma unroll
    for (int j = 0; j < 32; j += 8)
        g_WdT[(size_t)(bx + ty + j) * DIM_ + by + tx] = tile[tx][ty + j];
}

// ---------------------------------------------------------------------------
// Decode + loss
// ---------------------------------------------------------------------------
__global__ __launch_bounds__(256) void decode_kernel(
    const float* __restrict__ X, const float* __restrict__ b_dec,
    float* __restrict__ rec, float* __restrict__ loss)
{
    const int row = blockIdx.x;
    const int tid = threadIdx.x;
    __shared__ float sv[TOPK_];
    __shared__ int   si[TOPK_];
    if (tid < TOPK_) { sv[tid] = g_vals[row * TOPK_ + tid];
                       si[tid] = g_idx [row * TOPK_ + tid]; }
    __syncthreads();

    float acc[3];
    #pragma unroll
    for (int j = 0; j < 3; j++) acc[j] = b_dec[tid + j * 256];

    for (int kk = 0; kk < TOPK_; kk++) {
        const float* w = g_WdT + (size_t)si[kk] * DIM_;
        float v = sv[kk];
        #pragma unroll
        for (int j = 0; j < 3; j++)
            acc[j] = fmaf(v, w[tid + j * 256], acc[j]);
    }

    float err = 0.f;
    #pragma unroll
    for (int j = 0; j < 3; j++) {
        int d = tid + j * 256;
        float r = acc[j];
        rec[(size_t)row * DIM_ + d] = r;
        float diff = r - X[(size_t)row * DIM_ + d];
        err = fmaf(diff, diff, err);
    }
    #pragma unroll
    for (int o = 16; o; o >>= 1) err += __shfl_xor_sync(0xFFFFFFFFu, err, o);
    __shared__ float ws[8];
    if ((tid & 31) == 0) ws[tid >> 5] = err;
    __syncthreads();
    if (tid < 8) {
        float e = ws[tid];
        #pragma unroll
        for (int o = 4; o; o >>= 1) e += __shfl_xor_sync(0xFFu, e, o);
        if (tid == 0) atomicAdd(loss, e * (1.0f / BATCH_));
    }
}

__global__ void zero_loss(float* loss) { if (threadIdx.x == 0) *loss = 0.f; }

// ---------------------------------------------------------------------------
// kernel_launch
// ---------------------------------------------------------------------------
extern "C" void kernel_launch(void* const* d_in, const int* in_sizes, int n_in,
                              void* d_out, int out_size)
{
    const float* X     = (const float*)d_in[0];
    const float* W_enc = (const float*)d_in[1];
    const float* b_enc = (const float*)d_in[2];
    const float* W_dec = (const float*)d_in[3];
    const float* b_dec = (const float*)d_in[4];

    float* out  = (float*)d_out;
    float* rec  = out;
    float* enc  = out + (size_t)BATCH_ * DIM_;
    float* loss = enc + (size_t)BATCH_ * DICT_;

    cudaFuncSetAttribute(topk_cand,
                         cudaFuncAttributeMaxDynamicSharedMemorySize,
                         DICT_ * 2);
    cudaFuncSetAttribute(encode_gemm_mma,
                         cudaFuncAttributeMaxDynamicSharedMemorySize,
                         SMEM_GEMM);

    zero_enc<<<(int)((size_t)BATCH_ * DICT_ / 4 / 256), 256>>>(enc);
    cvt_x<<<(BATCH_ * DIM_ / 4 + 255) / 256, 256>>>(X);
    cvt_w<<<(DICT_ * DIM_ / 4 + 255) / 256, 256>>>(W_enc);

    dim3 gg(BATCH_ / TM, DICT_ / TN);
    encode_gemm_mma<<<gg, 256, SMEM_GEMM>>>(b_enc);

    topk_cand<<<BATCH_, 256, DICT_ * 2>>>();
    refine_kernel<<<BATCH_, 256>>>(X, W_enc, b_enc, enc);
    transpose_wdec<<<dim3(DICT_ / 32, DIM_ / 32), dim3(32, 8)>>>(W_dec);
    zero_loss<<<1, 32>>>(loss);
    decode_kernel<<<BATCH_, 256>>>(X, b_dec, rec, loss);
}

// round 10
// speedup vs baseline: 1.3714x; 1.3714x over previous
#include <cuda_runtime.h>
#include <cuda_bf16.h>
#include <cstdint>

#define BATCH_ 8192
#define DIM_   768
#define DICT_  32768
#define TOPK_  32
#define CAND   64

// Plain bf16 filter GEMM (refine makes the final result exact): K = 768
#define K2      768
#define TM      128
#define TN      128
#define BK      32
#define NCH     (K2 / BK)          // 24
#define ASTRIDE 80                 // 64B row + 16B pad: conflict-free ldmatrix
#define A_STAGE (TM * ASTRIDE)     // 10240
#define STAGE_BYTES (2 * A_STAGE)  // 20480
#define STAGES  4
#define SMEM_GEMM (STAGES * STAGE_BYTES)   // 81920

// ---------------------------------------------------------------------------
// Device scratch (allocation-free rule: __device__ globals)
// ---------------------------------------------------------------------------
__device__ __nv_bfloat16 g_XA[(size_t)BATCH_ * K2];    // bf16(X)
__device__ __nv_bfloat16 g_WB[(size_t)DICT_  * K2];    // bf16(W_enc)
__device__ __nv_bfloat16 g_Z [(size_t)BATCH_ * DICT_]; // approx z (bf16)
__device__ float g_WdT[(size_t)DICT_ * DIM_];          // W_dec transposed
__device__ int   g_cand[BATCH_ * CAND];                // approx top-64 indices
__device__ float g_vals[BATCH_ * TOPK_];
__device__ int   g_idx [BATCH_ * TOPK_];

// ---------------------------------------------------------------------------
// PTX helpers (sm_80+ baseline only — NO tcgen05: harness targets sm_103)
// ---------------------------------------------------------------------------
__device__ __forceinline__ uint32_t smem_u32(const void* p) {
    return (uint32_t)__cvta_generic_to_shared(p);
}

__device__ __forceinline__ void cp_async16(uint32_t dst, const void* src) {
    asm volatile("cp.async.cg.shared.global [%0], [%1], 16;"
                 :: "r"(dst), "l"(src) : "memory");
}

__device__ __forceinline__ void ldsm_x4(uint32_t r[4], uint32_t addr) {
    asm volatile("ldmatrix.sync.aligned.m8n8.x4.shared.b16 {%0,%1,%2,%3}, [%4];"
                 : "=r"(r[0]), "=r"(r[1]), "=r"(r[2]), "=r"(r[3]) : "r"(addr));
}

__device__ __forceinline__ void mma16816(float c[4], const uint32_t a[4],
                                         const uint32_t b[2]) {
    asm volatile(
        "mma.sync.aligned.m16n8k16.row.col.f32.bf16.bf16.f32 "
        "{%0,%1,%2,%3}, {%4,%5,%6,%7}, {%8,%9}, {%0,%1,%2,%3};"
        : "+f"(c[0]), "+f"(c[1]), "+f"(c[2]), "+f"(c[3])
        : "r"(a[0]), "r"(a[1]), "r"(a[2]), "r"(a[3]), "r"(b[0]), "r"(b[1]));
}

// ---------------------------------------------------------------------------
// fp32 -> bf16 conversions (vectorized)
// ---------------------------------------------------------------------------
__global__ __launch_bounds__(256) void cvt_x(const float* __restrict__ X) {
    int i = blockIdx.x * 256 + threadIdx.x;
    if (i >= BATCH_ * DIM_ / 4) return;
    float4 v = reinterpret_cast<const float4*>(X)[i];
    reinterpret_cast<__nv_bfloat162*>(g_XA)[i*2]   = __float22bfloat162_rn(make_float2(v.x, v.y));
    reinterpret_cast<__nv_bfloat162*>(g_XA)[i*2+1] = __float22bfloat162_rn(make_float2(v.z, v.w));
}

__global__ __launch_bounds__(256) void cvt_w(const float* __restrict__ W) {
    int i = blockIdx.x * 256 + threadIdx.x;
    if (i >= DICT_ * DIM_ / 4) return;
    float4 v = reinterpret_cast<const float4*>(W)[i];
    reinterpret_cast<__nv_bfloat162*>(g_WB)[i*2]   = __float22bfloat162_rn(make_float2(v.x, v.y));
    reinterpret_cast<__nv_bfloat162*>(g_WB)[i*2+1] = __float22bfloat162_rn(make_float2(v.z, v.w));
}

// ---------------------------------------------------------------------------
// HMMA filter GEMM: Z[m,n] = bf16( sum_k XA[m,k]*WB[n,k] + bias[n] )
// 128x128 CTA tile, BK=32, 8 warps (64x32 warp tiles), cp.async 4-slot ring.
// (R8-proven configuration: 2 CTAs/SM, tensor/smem co-bound.)
// ---------------------------------------------------------------------------
__device__ __forceinline__ void load_stage_g(uint32_t sbase, int slot, int k0,
                                             int m0, int n0, int tid) {
    uint32_t sA = sbase + slot * STAGE_BYTES;
    uint32_t sB = sA + A_STAGE;
    const __nv_bfloat16* Ag = g_XA + (size_t)m0 * K2 + k0;
    const __nv_bfloat16* Bg = g_WB + (size_t)n0 * K2 + k0;
    const int lrow = tid >> 2;       // 0..63
    const int lch  = tid & 3;        // 16B chunk within 64B row
    #pragma unroll
    for (int it = 0; it < 2; it++) {
        int row = lrow + it * 64;
        cp_async16(sA + row * ASTRIDE + lch * 16, Ag + (size_t)row * K2 + lch * 8);
        cp_async16(sB + row * ASTRIDE + lch * 16, Bg + (size_t)row * K2 + lch * 8);
    }
}

__global__ __launch_bounds__(256, 2) void encode_gemm_mma(
    const float* __restrict__ bias)
{
    extern __shared__ char smem[];
    const uint32_t sbase = smem_u32(smem);
    const int tid  = threadIdx.x;
    const int lane = tid & 31;
    const int wid  = tid >> 5;
    const int m0 = blockIdx.x * TM;
    const int n0 = blockIdx.y * TN;
    const int wm = (wid & 1) * 64;
    const int wn = (wid >> 1) * 32;

    float acc[4][4][4];
    #pragma unroll
    for (int mi = 0; mi < 4; mi++)
        #pragma unroll
        for (int ni = 0; ni < 4; ni++)
            #pragma unroll
            for (int r = 0; r < 4; r++) acc[mi][ni][r] = 0.f;

    #pragma unroll
    for (int s = 0; s < 3; s++) {
        load_stage_g(sbase, s, s * BK, m0, n0, tid);
        asm volatile("cp.async.commit_group;" ::: "memory");
    }

    for (int i = 0; i < NCH; i++) {
        asm volatile("cp.async.wait_group 2;" ::: "memory");
        __syncthreads();

        if (i + 3 < NCH)
            load_stage_g(sbase, (i + 3) & 3, (i + 3) * BK, m0, n0, tid);
        asm volatile("cp.async.commit_group;" ::: "memory");

        const uint32_t sA = sbase + (i & 3) * STAGE_BYTES;
        const uint32_t sB = sA + A_STAGE;
        const int g = lane >> 3;

        #pragma unroll
        for (int ks = 0; ks < 2; ks++) {
            uint32_t a[4][4], b[2][4];
            #pragma unroll
            for (int mi = 0; mi < 4; mi++)
                ldsm_x4(a[mi], sA + (wm + mi * 16 + (lane & 15)) * ASTRIDE
                               + ks * 32 + (lane >> 4) * 16);
            #pragma unroll
            for (int nj = 0; nj < 2; nj++)
                ldsm_x4(b[nj], sB + (wn + nj * 16 + (g >> 1) * 8 + (lane & 7)) * ASTRIDE
                               + ks * 32 + (g & 1) * 16);
            #pragma unroll
            for (int mi = 0; mi < 4; mi++)
                #pragma unroll
                for (int ni = 0; ni < 4; ni++)
                    mma16816(acc[mi][ni], a[mi], &b[ni >> 1][(ni & 1) * 2]);
        }
    }

    #pragma unroll
    for (int mi = 0; mi < 4; mi++) {
        int r0 = m0 + wm + mi * 16 + (lane >> 2);
        #pragma unroll
        for (int ni = 0; ni < 4; ni++) {
            int col = n0 + wn + ni * 8 + (lane & 3) * 2;
            float2 bv = *reinterpret_cast<const float2*>(bias + col);
            __nv_bfloat162 v0 = __float22bfloat162_rn(
                make_float2(acc[mi][ni][0] + bv.x, acc[mi][ni][1] + bv.y));
            __nv_bfloat162 v1 = __float22bfloat162_rn(
                make_float2(acc[mi][ni][2] + bv.x, acc[mi][ni][3] + bv.y));
            *reinterpret_cast<__nv_bfloat162*>(g_Z + (size_t)r0 * DICT_ + col)       = v0;
            *reinterpret_cast<__nv_bfloat162*>(g_Z + (size_t)(r0 + 8) * DICT_ + col) = v1;
        }
    }
}

// ---------------------------------------------------------------------------
// Candidate selection on bf16 z: top-CAND indices per row.
// Three FULL scans of the 64KB smem row (R8-proven plain atomics).
// ALSO zeroes this row of the encoded output (fuses the old zero_enc kernel;
// the 128KB of streaming writes hide under the smem scans).
// ---------------------------------------------------------------------------
__device__ __forceinline__ unsigned key16(unsigned h) {
    return h ^ ((h & 0x8000u) ? 0xFFFFu : 0x8000u);
}

__global__ __launch_bounds__(256) void topk_cand(float* __restrict__ enc)
{
    extern __shared__ unsigned short srow16[];   // DICT_ uint16 = 64KB
    const int row = blockIdx.x;
    const int tid = threadIdx.x;

    {
        const uint4* z4 = reinterpret_cast<const uint4*>(g_Z + (size_t)row * DICT_);
        uint4* s4 = reinterpret_cast<uint4*>(srow16);
        for (int i = tid; i < DICT_ * 2 / 16; i += 256) s4[i] = z4[i];
    }

    // Fused zeroing of this row of the encoded output (independent of scans;
    // refine scatters the 32 exact values afterwards).
    {
        float4 zero = make_float4(0.f, 0.f, 0.f, 0.f);
        float4* e4 = reinterpret_cast<float4*>(enc + (size_t)row * DICT_);
        for (int i = tid; i < DICT_ / 4; i += 256) e4[i] = zero;
    }

    __shared__ unsigned hist[256];
    __shared__ int s_b, s_k, s_b2, s_k2, nslot, eq2;

    if (tid == 0) { nslot = 0; eq2 = 0; }
    hist[tid] = 0;
    __syncthreads();

    // scan1: high-byte histogram (2 elems per 32-bit smem read)
    for (int i = tid; i < DICT_ / 2; i += 256) {
        unsigned v = reinterpret_cast<unsigned*>(srow16)[i];
        atomicAdd(&hist[key16(v & 0xFFFFu) >> 8], 1u);
        atomicAdd(&hist[key16(v >> 16) >> 8], 1u);
    }
    __syncthreads();
    if (tid == 0) {
        int kk = CAND, b = 255;
        for (;; b--) { int c = (int)hist[b]; if (c >= kk) break; kk -= c; }
        s_b = b; s_k = kk;
    }
    __syncthreads();
    const unsigned bhi = (unsigned)s_b;
    const int keq1 = s_k;
    hist[tid] = 0;
    __syncthreads();

    // scan2: low-byte histogram restricted to hi == bhi
    for (int i = tid; i < DICT_ / 2; i += 256) {
        unsigned v = reinterpret_cast<unsigned*>(srow16)[i];
        unsigned k0 = key16(v & 0xFFFFu);
        unsigned k1 = key16(v >> 16);
        if ((k0 >> 8) == bhi) atomicAdd(&hist[k0 & 0xFFu], 1u);
        if ((k1 >> 8) == bhi) atomicAdd(&hist[k1 & 0xFFu], 1u);
    }
    __syncthreads();
    if (tid == 0) {
        int kk = keq1, b = 255;
        for (;; b--) { int c = (int)hist[b]; if (c >= kk) break; kk -= c; }
        s_b2 = b; s_k2 = kk;
    }
    __syncthreads();
    const unsigned blo = (unsigned)s_b2;
    const int keq2 = s_k2;

    // scan3: emit exactly CAND candidate indices
    for (int i = tid; i < DICT_; i += 256) {
        unsigned k = key16(srow16[i]);
        unsigned hi = k >> 8, lo = k & 0xFFu;
        if (hi > bhi || (hi == bhi && lo > blo)) {
            int s = atomicAdd(&nslot, 1);
            g_cand[row * CAND + s] = i;
        } else if (hi == bhi && lo == blo) {
            int e = atomicAdd(&eq2, 1);
            if (e < keq2) {
                int s = atomicAdd(&nslot, 1);
                g_cand[row * CAND + s] = i;
            }
        }
    }
}

// ---------------------------------------------------------------------------
// Refine: exact fp32 recompute of the CAND candidates, exact top-32 with
// first-index tie-break, scatter into enc + decode buffers.
// ---------------------------------------------------------------------------
__device__ __forceinline__ unsigned key_of(float f) {
    unsigned u = __float_as_uint(f);
    return u ^ ((u & 0x80000000u) ? 0xFFFFFFFFu : 0x80000000u);
}

__device__ __forceinline__ unsigned long long sel_key(float v, int idx) {
    return ((unsigned long long)key_of(v) << 32) | (unsigned)(0x7FFFFFFF - idx);
}

__global__ __launch_bounds__(256) void refine_kernel(
    const float* __restrict__ X, const float* __restrict__ W_enc,
    const float* __restrict__ b_enc, float* __restrict__ enc)
{
    const int row = blockIdx.x;
    const int tid = threadIdx.x;
    const int w = tid >> 5, lane = tid & 31;
    __shared__ float sx[DIM_];
    __shared__ float cv[CAND];
    __shared__ int   ci[CAND];

    for (int i = tid; i < DIM_ / 4; i += 256)
        reinterpret_cast<float4*>(sx)[i] =
            reinterpret_cast<const float4*>(X + (size_t)row * DIM_)[i];
    if (tid < CAND) ci[tid] = g_cand[row * CAND + tid];
    __syncthreads();

    for (int c = w; c < CAND; c += 8) {
        const float* wr = W_enc + (size_t)ci[c] * DIM_;
        float s = 0.f;
        #pragma unroll
        for (int j = lane * 4; j < DIM_; j += 128) {
            float4 a = *reinterpret_cast<const float4*>(sx + j);
            float4 b = *reinterpret_cast<const float4*>(wr + j);
            s = fmaf(a.x, b.x, s); s = fmaf(a.y, b.y, s);
            s = fmaf(a.z, b.z, s); s = fmaf(a.w, b.w, s);
        }
        #pragma unroll
        for (int o = 16; o; o >>= 1) s += __shfl_xor_sync(0xFFFFFFFFu, s, o);
        if (lane == 0) cv[c] = s + b_enc[ci[c]];
    }
    __syncthreads();

    if (w == 0) {
        unsigned long long ka = sel_key(cv[lane],      ci[lane]);
        unsigned long long kb = sel_key(cv[lane + 32], ci[lane + 32]);
        for (int s = 0; s < TOPK_; s++) {
            unsigned long long m = ka > kb ? ka : kb;
            #pragma unroll
            for (int o = 16; o; o >>= 1) {
                unsigned long long t = __shfl_xor_sync(0xFFFFFFFFu, m, o);
                if (t > m) m = t;
            }
            if (ka == m) {
                int idx = ci[lane]; float v = cv[lane];
                enc[(size_t)row * DICT_ + idx] = v;
                g_vals[row * TOPK_ + s] = v;
                g_idx [row * TOPK_ + s] = idx;
                ka = 0ull;
            } else if (kb == m) {
                int idx = ci[lane + 32]; float v = cv[lane + 32];
                enc[(size_t)row * DICT_ + idx] = v;
                g_vals[row * TOPK_ + s] = v;
                g_idx [row * TOPK_ + s] = idx;
                kb = 0ull;
            }
        }
    }
}

// ---------------------------------------------------------------------------
// W_dec [DIM, DICT] -> g_WdT [DICT, DIM]
// ---------------------------------------------------------------------------
__global__ void transpose_wdec(const float* __restrict__ Wd)
{
    __shared__ float tile[32][33];
    int bx = blockIdx.x * 32;
    int by = blockIdx.y * 32;
    int tx = threadIdx.x, ty = threadIdx.y;
    #pragma unroll
    for (int j = 0; j < 32; j += 8)
        tile[ty + j][tx] = Wd[(size_t)(by + ty + j) * DICT_ + bx + tx];
    __syncthreads();
    #pragma unroll
    for (int j = 0; j < 32; j += 8)
        g_WdT[(size_t)(bx + ty + j) * DIM_ + by + tx] = tile[tx][ty + j];
}

// ---------------------------------------------------------------------------
// Decode + loss
// ---------------------------------------------------------------------------
__global__ __launch_bounds__(256) void decode_kernel(
    const float* __restrict__ X, const float* __restrict__ b_dec,
    float* __restrict__ rec, float* __restrict__ loss)
{
    const int row = blockIdx.x;
    const int tid = threadIdx.x;
    __shared__ float sv[TOPK_];
    __shared__ int   si[TOPK_];
    if (tid < TOPK_) { sv[tid] = g_vals[row * TOPK_ + tid];
                       si[tid] = g_idx [row * TOPK_ + tid]; }
    __syncthreads();

    float acc[3];
    #pragma unroll
    for (int j = 0; j < 3; j++) acc[j] = b_dec[tid + j * 256];

    for (int kk = 0; kk < TOPK_; kk++) {
        const float* w = g_WdT + (size_t)si[kk] * DIM_;
        float v = sv[kk];
        #pragma unroll
        for (int j = 0; j < 3; j++)
            acc[j] = fmaf(v, w[tid + j * 256], acc[j]);
    }

    float err = 0.f;
    #pragma unroll
    for (int j = 0; j < 3; j++) {
        int d = tid + j * 256;
        float r = acc[j];
        rec[(size_t)row * DIM_ + d] = r;
        float diff = r - X[(size_t)row * DIM_ + d];
        err = fmaf(diff, diff, err);
    }
    #pragma unroll
    for (int o = 16; o; o >>= 1) err += __shfl_xor_sync(0xFFFFFFFFu, err, o);
    __shared__ float ws[8];
    if ((tid & 31) == 0) ws[tid >> 5] = err;
    __syncthreads();
    if (tid < 8) {
        float e = ws[tid];
        #pragma unroll
        for (int o = 4; o; o >>= 1) e += __shfl_xor_sync(0xFFu, e, o);
        if (tid == 0) atomicAdd(loss, e * (1.0f / BATCH_));
    }
}

__global__ void zero_loss(float* loss) { if (threadIdx.x == 0) *loss = 0.f; }

// ---------------------------------------------------------------------------
// kernel_launch
// ---------------------------------------------------------------------------
extern "C" void kernel_launch(void* const* d_in, const int* in_sizes, int n_in,
                              void* d_out, int out_size)
{
    const float* X     = (const float*)d_in[0];
    const float* W_enc = (const float*)d_in[1];
    const float* b_enc = (const float*)d_in[2];
    const float* W_dec = (const float*)d_in[3];
    const float* b_dec = (const float*)d_in[4];

    float* out  = (float*)d_out;
    float* rec  = out;
    float* enc  = out + (size_t)BATCH_ * DIM_;
    float* loss = enc + (size_t)BATCH_ * DICT_;

    cudaFuncSetAttribute(topk_cand,
                         cudaFuncAttributeMaxDynamicSharedMemorySize,
                         DICT_ * 2);
    cudaFuncSetAttribute(encode_gemm_mma,
                         cudaFuncAttributeMaxDynamicSharedMemorySize,
                         SMEM_GEMM);

    cvt_x<<<(BATCH_ * DIM_ / 4 + 255) / 256, 256>>>(X);
    cvt_w<<<(DICT_ * DIM_ / 4 + 255) / 256, 256>>>(W_enc);

    // grid.x = M tiles (fast-varying) so a wave of CTAs shares B tiles in L2
    dim3 gg(BATCH_ / TM, DICT_ / TN);
    encode_gemm_mma<<<gg, 256, SMEM_GEMM>>>(b_enc);

    topk_cand<<<BATCH_, 256, DICT_ * 2>>>(enc);
    refine_kernel<<<BATCH_, 256>>>(X, W_enc, b_enc, enc);
    transpose_wdec<<<dim3(DICT_ / 32, DIM_ / 32), dim3(32, 8)>>>(W_dec);
    zero_loss<<<1, 32>>>(loss);
    decode_kernel<<<BATCH_, 256>>>(X, b_dec, rec, loss);
}